// round 11
// baseline (speedup 1.0000x reference)
#include <cuda_runtime.h>
#include <cstdint>

#define Bt    1024
#define Tt    1000
#define HH    256
#define NBLK  128
#define NTHR  512
#define ICC   32              // W2/W3 rows resident in SMEM
#define CHROWS 16             // rows per streamed chunk
#define NCHL  14              // chunks per layer: (256-32)/16
#define NGRP  7               // pair-groups per layer
#define NGTOT 14              // total groups (2 layers)
#define NSTG  6               // SMEM stages (3 pair-groups resident)

using u64 = unsigned long long;

__device__ __forceinline__ u64 ffma2(u64 a, u64 b, u64 c) {
    u64 d; asm("fma.rn.f32x2 %0,%1,%2,%3;" : "=l"(d) : "l"(a), "l"(b), "l"(c)); return d;
}
__device__ __forceinline__ u64 addf2(u64 a, u64 b) {
    u64 d; asm("add.rn.f32x2 %0,%1,%2;" : "=l"(d) : "l"(a), "l"(b)); return d;
}
__device__ __forceinline__ u64 pack2(float x, float y) {
    u64 d; asm("mov.b64 %0,{%1,%2};" : "=l"(d) : "f"(x), "f"(y)); return d;
}
__device__ __forceinline__ float2 unpack2(u64 a) {
    float2 f; asm("mov.b64 {%0,%1},%2;" : "=f"(f.x), "=f"(f.y) : "l"(a)); return f;
}
__device__ __forceinline__ float elu1(float v) { return v > 0.f ? v : (__expf(v) - 1.f); }

// non-dup activation row: 8 floats + 16B pad per 4 rows; HROW(4n+kq)=36n+8kq
#define HROW(i) ((i) * 8 + ((i) >> 2) * 4)

// ---------------- SMEM layout (float offsets) ----------------
#define OFF_W2   0                      // 32*256 = 8192
#define OFF_W3   8192                   // 8192
#define OFF_STR  16384                  // 6*16*256 = 24576
#define OFF_HA   40960                  // 2304
#define OFF_HB   43264                  // 2304
#define OFF_H3   45568                  // 8*260 = 2080
#define OFF_W4   47648                  // 8*260 = 2080
#define OFF_WXZ  49728                  // 16*256 = 4096
#define OFF_INP  53824                  // 144 (16 rows, HROW layout)
#define OFF_RED  53968                  // 512 (also araw scratch)
#define OFF_ZJ   54480                  // 64
#define OFF_EVT  54544                  // 8
#define OFF_B4   54552                  // 8
#define OFF_TSH  54560                  // 2
#define SM_FLOATS 54562
#define SM_BYTES  (SM_FLOATS * 4)       // 218248 B (< 232448 cap)

#define STG_FLOATS (CHROWS * HH)        // 4096

// one weight-row accumulation (j-pair): acc[jj*4+gp] += dup(w_jj) * (h_2gp,h_2gp+1)
__device__ __forceinline__ void accum_p(const float* __restrict__ w8,
                                        const float* __restrict__ h8,
                                        u64* __restrict__ acc) {
    float2 w = *(const float2*)w8;                   // (w_j0, w_j1)
    u64 wd0 = pack2(w.x, w.x), wd1 = pack2(w.y, w.y);
    ulonglong2 hlo = *(const ulonglong2*)h8;         // (g0,g1),(g2,g3)
    ulonglong2 hhi = *(const ulonglong2*)(h8 + 4);   // (g4,g5),(g6,g7)
    acc[0] = ffma2(hlo.x, wd0, acc[0]); acc[1] = ffma2(hlo.y, wd0, acc[1]);
    acc[2] = ffma2(hhi.x, wd0, acc[2]); acc[3] = ffma2(hhi.y, wd0, acc[3]);
    acc[4] = ffma2(hlo.x, wd1, acc[4]); acc[5] = ffma2(hlo.y, wd1, acc[5]);
    acc[6] = ffma2(hhi.x, wd1, acc[6]); acc[7] = ffma2(hhi.y, wd1, acc[7]);
}

// issue one pair-group (2 chunks of 16 rows) as a single commit group
__device__ __forceinline__ void issue_group(int g, unsigned str_u32,
                                            const float* __restrict__ W2,
                                            const float* __restrict__ W3, int tid) {
    if (g >= NGTOT) return;
#pragma unroll
    for (int h = 0; h < 2; h++) {
        const int k = g * 2 + h;
        const int kl = (k < NCHL) ? k : (k - NCHL);
        const char* src = (const char*)((k < NCHL ? W2 : W3) + (ICC + kl * CHROWS) * HH);
        unsigned dst = str_u32 + (unsigned)(k % NSTG) * (STG_FLOATS * 4);
#pragma unroll
        for (int r = 0; r < 2; r++) {
            unsigned off = (unsigned)(tid + r * NTHR) * 16;
            asm volatile("cp.async.cg.shared.global [%0], [%1], 16;" :: "r"(dst + off), "l"(src + off));
        }
    }
    asm volatile("cp.async.commit_group;");
}

// full 256->256 layer (512 thr): j-pair x 8 batches x K-quarter
template <bool TO_H3P>
__device__ __forceinline__ void biglayerP(
    const float* __restrict__ wc, const float* __restrict__ strb,
    const float* __restrict__ W2, const float* __restrict__ W3,
    const float* __restrict__ hsrc, float* __restrict__ hdst,
    int j0, int kq, int layer, float2 bb,
    unsigned str_u32, int tid)
{
    u64 acc[8];
#pragma unroll
    for (int q = 0; q < 8; q++) acc[q] = 0ull;

    const float* wt = wc + kq * HH + j0;      // cached-weight lane base
    const float* ht = hsrc + kq * 8;          // h lane base: HROW(4n+kq)=36n+8kq

    // cached rows: n = 0..7 (row 4n+kq)
#pragma unroll
    for (int n = 0; n < ICC / 4; n++)
        accum_p(wt + n * 4 * HH, ht + n * 36, acc);

    // streamed pair-groups: 7 per layer, 8 accum iterations each
#pragma unroll 1
    for (int gp = 0; gp < NGRP; gp++) {
        const int g = layer * NGRP + gp;
        if (g < NGTOT - 1) asm volatile("cp.async.wait_group 1;" ::: "memory");
        else               asm volatile("cp.async.wait_group 0;" ::: "memory");
        __syncthreads();
        issue_group(g + 2, str_u32, W2, W3, tid);
#pragma unroll
        for (int h = 0; h < 2; h++) {
            const int k = g * 2 + h;
            const float* sb = strb + (k % NSTG) * STG_FLOATS + kq * HH + j0;
            const int nbase = ICC / 4 + (gp * 2 + h) * 4;
#pragma unroll
            for (int m = 0; m < 4; m++)
                accum_p(sb + m * 4 * HH, ht + (nbase + m) * 36, acc);
        }
    }

    // K-reduction across kq via shuffles (lanes ^8, ^16)
#pragma unroll
    for (int q = 0; q < 8; q++) {
        acc[q] = addf2(acc[q], __shfl_xor_sync(0xffffffffu, acc[q], 8));
        acc[q] = addf2(acc[q], __shfl_xor_sync(0xffffffffu, acc[q], 16));
    }

    // lane finalizes g-pair gp = kq for its 2 j's
    float2 va = unpack2(acc[kq]);        // j0: g 2kq, 2kq+1
    float2 vb = unpack2(acc[4 + kq]);    // j1
    float a0 = elu1(va.x + bb.x), a1 = elu1(va.y + bb.x);
    float b0 = elu1(vb.x + bb.y), b1 = elu1(vb.y + bb.y);

    if (TO_H3P) {
        *(float2*)(hdst + (2 * kq) * 260 + j0)     = make_float2(a0, b0);
        *(float2*)(hdst + (2 * kq + 1) * 260 + j0) = make_float2(a1, b1);
    } else {
        float* wb = hdst + HROW(j0) + 2 * kq;      // HROW(j0+1)=HROW(j0)+8
        *(u64*)(wb)     = pack2(a0, a1);
        *(u64*)(wb + 8) = pack2(b0, b1);
    }
}

__global__ __launch_bounds__(NTHR, 1)
void ode_main(const float* __restrict__ t, const float* __restrict__ x,
              const float* __restrict__ z, const float* __restrict__ event_t,
              const float* __restrict__ z_jump,
              const float* __restrict__ W1, const float* __restrict__ b1,
              const float* __restrict__ W2, const float* __restrict__ b2,
              const float* __restrict__ W3, const float* __restrict__ b3,
              const float* __restrict__ W4, const float* __restrict__ b4,
              float* __restrict__ out)
{
    extern __shared__ float sm[];
    float* w2c  = sm + OFF_W2;
    float* w3c  = sm + OFF_W3;
    float* strb = sm + OFF_STR;
    float* hA   = sm + OFF_HA;
    float* hB   = sm + OFF_HB;
    float* h3p  = sm + OFF_H3;
    float* w4t  = sm + OFF_W4;
    float* wxzs = sm + OFF_WXZ;
    float* inp  = sm + OFF_INP;
    float* red  = sm + OFF_RED;
    float* zjs  = sm + OFF_ZJ;
    float* evts = sm + OFF_EVT;
    float* b4s  = sm + OFF_B4;
    float* tsh  = sm + OFF_TSH;

    const int tid = threadIdx.x;
    const int b0  = blockIdx.x * 8;
    const unsigned str_u32 = (unsigned)__cvta_generic_to_shared(strb);

    // ---- lane decompositions ----
    const int lane = tid & 31, warp = tid >> 5;
    // big layers: j-pair x 8 batches x K-quarter
    const int pib = warp * 8 + (lane & 7);     // pair index 0..127
    const int j0b = pib * 2;
    const int kq  = lane >> 3;                 // 0..3
    // layer 1: j-pair x 2 batches
    const int pr  = tid & 127;                 // pair 0..127
    const int j0  = pr * 2;
    const int gq  = tid >> 7;                  // 0..3 -> batches 2gq, 2gq+1

    // ---- init: SMEM caches + raw inputs ----
    for (int idx = tid; idx < ICC * HH; idx += NTHR) { w2c[idx] = W2[idx]; w3c[idx] = W3[idx]; }
    for (int idx = tid; idx < 8 * HH; idx += NTHR) {
        int k = idx >> 8, i = idx & 255;
        w4t[k * 260 + i] = W4[i * 8 + k];
    }
    for (int idx = tid; idx < 16 * HH; idx += NTHR) {
        int i = idx >> 8, j = idx & 255;
        wxzs[idx] = W1[(16 + i) * HH + j] + W1[(32 + i) * HH + j];
    }
    if (tid < 8) { evts[tid] = event_t[b0 + tid]; b4s[tid] = b4[tid]; }
    if (tid < 64) { int g = tid >> 3, i = tid & 7; zjs[tid] = z_jump[(b0 + g) * 8 + i]; }
    if (tid == 0) { tsh[0] = t[0]; tsh[1] = t[1]; }

    float zreg = 0.f; size_t zbase = 0;
    if (tid >= 64 && tid < 128) {
        int r = tid - 64, g = r >> 3, i = r & 7;
        zbase = (size_t)(b0 + g) * Tt * 8 + i;
    }
    float treg = 0.f;
    if (tid == 192) treg = t[2];

    if (tid < 64) {
        int k = tid & 7, g = tid >> 3;
        float xv = x[(size_t)(b0 + g) * Tt * 8 + k];
        red[k * 8 + g] = xv;
        inp[HROW(k) + g] = xv;
        out[(size_t)(b0 + g) * Tt * 8 + k] = xv;
    } else if (tid < 128) {
        int r = tid - 64, g = r >> 3, zi = r & 7;
        float z0 = z[zbase];
        red[(8 + zi) * 8 + g] = z0;
        zreg = z[zbase + 8];
    }
    __syncthreads();

    if (tid >= 64 && tid < 128) {
        int r = tid - 64, g = r >> 3, zi = r & 7;
        float v = (tsh[0] >= evts[g]) ? zjs[r] : red[(8 + zi) * 8 + g];
        inp[HROW(8 + zi) + g] = v;
    }

    // per-thread layer-1 cinit (j-pair x 2 batches)
    u64 cig0, cig1;
    {
        float2 bb = *(const float2*)&b1[j0];
        float c00 = bb.x, c01 = bb.x, c10 = bb.y, c11 = bb.y;
#pragma unroll
        for (int i = 0; i < 16; i++) {
            float2 wa = *(const float2*)&W1[i * HH + j0];
            float2 wb = *(const float2*)&W1[(16 + i) * HH + j0];
            float a0 = red[i * 8 + 2 * gq], a1 = red[i * 8 + 2 * gq + 1];
            float dx = wa.x - wb.x, dy = wa.y - wb.y;
            c00 = fmaf(a0, dx, c00); c01 = fmaf(a1, dx, c01);
            c10 = fmaf(a0, dy, c10); c11 = fmaf(a1, dy, c11);
        }
        cig0 = pack2(c00, c01); cig1 = pack2(c10, c11);
    }
    const float2 b2p = *(const float2*)&b2[j0b];
    const float2 b3p = *(const float2*)&b3[j0b];

    // layer-4 mapping: 8-way K split
    const int c4 = tid >> 6, r4 = tid & 63, k4 = r4 & 7, g4 = r4 >> 3;
    __syncthreads();

    for (int s = 0; s < Tt - 1; s++) {
        const float t0 = tsh[s & 1];
        const float t1 = tsh[(s + 1) & 1];
        const float dt = t1 - t0;

        // stream prologue: 2 pair-groups in flight during layer 1
        issue_group(0, str_u32, W2, W3, tid);
        issue_group(1, str_u32, W2, W3, tid);

        // ---- layer 1 (K=16, folded) ----
        {
            u64 acc0 = cig0, acc1 = cig1;
#pragma unroll
            for (int i = 0; i < 16; i++) {
                u64 hv = *(const u64*)(inp + HROW(i) + 2 * gq);
                float2 wp = *(const float2*)(wxzs + i * HH + j0);
                acc0 = ffma2(hv, pack2(wp.x, wp.x), acc0);
                acc1 = ffma2(hv, pack2(wp.y, wp.y), acc1);
            }
            float2 v0 = unpack2(acc0), v1 = unpack2(acc1);
            float* wb = hA + HROW(j0) + 2 * gq;
            *(u64*)(wb)     = pack2(elu1(v0.x), elu1(v0.y));
            *(u64*)(wb + 8) = pack2(elu1(v1.x), elu1(v1.y));
        }
        __syncthreads();

        // t rolling slot + z prefetch for step s+2
        if (tid == 192) {
            if (s + 2 < Tt) tsh[s & 1] = treg;
            if (s + 3 < Tt) treg = t[s + 3];
        }
        float znext = 0.f;
        if (tid >= 64 && tid < 128 && s + 2 < Tt) znext = z[zbase + (size_t)(s + 2) * 8];

        // ---- layer 2 ----
        biglayerP<false>(w2c, strb, W2, W3, hA, hB, j0b, kq, 0, b2p, str_u32, tid);
        __syncthreads();

        // ---- layer 3 ----
        biglayerP<true>(w3c, strb, W2, W3, hB, h3p, j0b, kq, 1, b3p, str_u32, tid);
        __syncthreads();

        // ---- layer 4 partials (8-way K split) ----
        {
            float p = 0.f;
            const int base = c4 * 32;
            const float* hp = h3p + g4 * 260 + base;
            const float* wp = w4t + k4 * 260 + base;
#pragma unroll
            for (int it = 0; it < 8; it++) {
                float4 hv = *(const float4*)(hp + it * 4);
                float4 wv = *(const float4*)(wp + it * 4);
                p = fmaf(hv.x, wv.x, p); p = fmaf(hv.y, wv.y, p);
                p = fmaf(hv.z, wv.z, p); p = fmaf(hv.w, wv.w, p);
            }
            red[tid] = p;
        }
        __syncthreads();

        // ---- epilogue ----
        if (tid < 64) {
            int k = tid & 7, g = tid >> 3;
            float o = b4s[k];
#pragma unroll
            for (int m = 0; m < 8; m++) o += red[tid + 64 * m];
            float xn = inp[HROW(k) + g] + dt * o;
            inp[HROW(k) + g] = xn;
            out[(size_t)(b0 + g) * Tt * 8 + (size_t)(s + 1) * 8 + k] = xn;
        } else if (tid < 128) {
            int r = tid - 64, g = r >> 3, zi = r & 7;
            float v = (t1 >= evts[g]) ? zjs[r] : zreg;
            inp[HROW(8 + zi) + g] = v;
            zreg = znext;
        }
        __syncthreads();
    }
}

extern "C" void kernel_launch(void* const* d_in, const int* in_sizes, int n_in,
                              void* d_out, int out_size) {
    const float* t       = (const float*)d_in[0];
    const float* x       = (const float*)d_in[1];
    const float* z       = (const float*)d_in[2];
    const float* event_t = (const float*)d_in[3];
    const float* z_jump  = (const float*)d_in[4];
    const float* W1      = (const float*)d_in[5];
    const float* b1      = (const float*)d_in[6];
    const float* W2      = (const float*)d_in[7];
    const float* b2      = (const float*)d_in[8];
    const float* W3      = (const float*)d_in[9];
    const float* b3      = (const float*)d_in[10];
    const float* W4      = (const float*)d_in[11];
    const float* b4      = (const float*)d_in[12];
    float* out = (float*)d_out;

    cudaFuncSetAttribute(ode_main, cudaFuncAttributeMaxDynamicSharedMemorySize, SM_BYTES);

    ode_main<<<NBLK, NTHR, SM_BYTES>>>(t, x, z, event_t, z_jump,
                                       W1, b1, W2, b2, W3, b3, W4, b4, out);
}

// round 14
// speedup vs baseline: 1.2704x; 1.2704x over previous
#include <cuda_runtime.h>
#include <cstdint>

#define Bt    1024
#define Tt    1000
#define HH    256
#define NBLK  128
#define NTHR  256
#define ICC   48
#define CHROWS 16
#define NCHL  13
#define NKTOT (2*NCHL)
#define NSTG  5

using u64 = unsigned long long;

__device__ __forceinline__ u64 ffma2(u64 a, u64 b, u64 c) {
    u64 d; asm("fma.rn.f32x2 %0,%1,%2,%3;" : "=l"(d) : "l"(a), "l"(b), "l"(c)); return d;
}
__device__ __forceinline__ u64 addf2(u64 a, u64 b) {
    u64 d; asm("add.rn.f32x2 %0,%1,%2;" : "=l"(d) : "l"(a), "l"(b)); return d;
}
__device__ __forceinline__ u64 pack2(float x, float y) {
    u64 d; asm("mov.b64 %0,{%1,%2};" : "=l"(d) : "f"(x), "f"(y)); return d;
}
__device__ __forceinline__ float2 unpack2(u64 a) {
    float2 f; asm("mov.b64 {%0,%1},%2;" : "=f"(f.x), "=f"(f.y) : "l"(a)); return f;
}
__device__ __forceinline__ float elu1(float v) { return v > 0.f ? v : (__expf(v) - 1.f); }

#define HROW(i) ((i) * 8 + ((i) >> 2) * 4)

#define OFF_W2   0
#define OFF_W3   12288
#define OFF_STR  24576
#define OFF_HA   45056
#define OFF_HB   47360
#define OFF_H3   49664
#define OFF_W4   51744
#define OFF_INP  53824
#define OFF_RED  53968
#define OFF_ZJ   54224
#define OFF_EVT  54288
#define OFF_B4   54296
#define OFF_TSH  54304
#define SM_FLOATS 54306
#define SM_BYTES  (SM_FLOATS * 4)

#define STG_FLOATS (CHROWS * HH)

__device__ __forceinline__ void accum_iter(const float* __restrict__ w16,
                                           const float* __restrict__ h8,
                                           u64* __restrict__ acc) {
    ulonglong2 w = *(const ulonglong2*)w16;
    float2 wl = unpack2(w.x), wh = unpack2(w.y);
    u64 wd0 = pack2(wl.x, wl.x), wd1 = pack2(wl.y, wl.y);
    u64 wd2 = pack2(wh.x, wh.x), wd3 = pack2(wh.y, wh.y);
    ulonglong2 hlo = *(const ulonglong2*)h8;
    ulonglong2 hhi = *(const ulonglong2*)(h8 + 4);
    acc[0]  = ffma2(hlo.x, wd0, acc[0]);  acc[1]  = ffma2(hlo.y, wd0, acc[1]);
    acc[2]  = ffma2(hhi.x, wd0, acc[2]);  acc[3]  = ffma2(hhi.y, wd0, acc[3]);
    acc[4]  = ffma2(hlo.x, wd1, acc[4]);  acc[5]  = ffma2(hlo.y, wd1, acc[5]);
    acc[6]  = ffma2(hhi.x, wd1, acc[6]);  acc[7]  = ffma2(hhi.y, wd1, acc[7]);
    acc[8]  = ffma2(hlo.x, wd2, acc[8]);  acc[9]  = ffma2(hlo.y, wd2, acc[9]);
    acc[10] = ffma2(hhi.x, wd2, acc[10]); acc[11] = ffma2(hhi.y, wd2, acc[11]);
    acc[12] = ffma2(hlo.x, wd3, acc[12]); acc[13] = ffma2(hlo.y, wd3, acc[13]);
    acc[14] = ffma2(hhi.x, wd3, acc[14]); acc[15] = ffma2(hhi.y, wd3, acc[15]);
}

// per-warp streamed-chunk issue: each lane copies exactly the 4x16B slices
// it will later read; visibility via cp.async.wait_group alone (no barriers).
__device__ __forceinline__ void issue_chunk_w(int k, unsigned str_u32,
                                              const float* __restrict__ W2,
                                              const float* __restrict__ W3,
                                              int warp, int lane) {
    if (k >= NKTOT) return;
    const int kl = (k < NCHL) ? k : (k - NCHL);
    const float* base = (k < NCHL ? W2 : W3) + (ICC + kl * CHROWS) * HH;
    const char* src = (const char*)(base + warp * 32) + (lane & 7) * 16;
    unsigned dst = str_u32 + (unsigned)(k % NSTG) * (STG_FLOATS * 4)
                 + (unsigned)warp * 128 + (unsigned)(lane & 7) * 16;
    const int r0 = lane >> 3;
#pragma unroll
    for (int wv = 0; wv < 4; wv++) {
        unsigned roff = (unsigned)(wv * 4 + r0) * (HH * 4);
        asm volatile("cp.async.cg.shared.global [%0], [%1], 16;"
                     :: "r"(dst + roff), "l"(src + roff));
    }
    asm volatile("cp.async.commit_group;");
}

template <bool TO_H3P>
__device__ __forceinline__ void biglayerA(
    const float* __restrict__ wc, const float* __restrict__ strb,
    const float* __restrict__ W2, const float* __restrict__ W3,
    const float* __restrict__ hsrc, float* __restrict__ hdst,
    int j0q, int kq, int quadg, int layer, ulonglong2 bq,
    unsigned str_u32, int warp, int lane)
{
    u64 acc[16];
#pragma unroll
    for (int q = 0; q < 16; q++) acc[q] = 0ull;

    const float* wt = wc + kq * HH + j0q;
    const float* ht = hsrc + kq * 8;

#pragma unroll 4
    for (int n = 0; n < ICC / 4; n++)
        accum_iter(wt + n * 4 * HH, ht + n * 36, acc);

#pragma unroll 1
    for (int c = 0; c < NCHL; c++) {
        const int k = layer * NCHL + c;
        if (k < NKTOT - 2)       asm volatile("cp.async.wait_group 2;" ::: "memory");
        else if (k == NKTOT - 2) asm volatile("cp.async.wait_group 1;" ::: "memory");
        else                     asm volatile("cp.async.wait_group 0;" ::: "memory");
        issue_chunk_w(k + 3, str_u32, W2, W3, warp, lane);
        const float* sb = strb + (k % NSTG) * STG_FLOATS + kq * HH + j0q;
        const int nbase = ICC / 4 + c * 4;
#pragma unroll
        for (int m = 0; m < 4; m++)
            accum_iter(sb + m * 4 * HH, ht + (nbase + m) * 36, acc);
    }

#pragma unroll
    for (int q = 0; q < 16; q++) {
        acc[q] = addf2(acc[q], __shfl_xor_sync(0xffffffffu, acc[q], 8));
        acc[q] = addf2(acc[q], __shfl_xor_sync(0xffffffffu, acc[q], 16));
    }

    float2 blo = unpack2(bq.x), bhi = unpack2(bq.y);
    const float bj[4] = { blo.x, blo.y, bhi.x, bhi.y };
    float vx[4], vy[4];
#pragma unroll
    for (int jj = 0; jj < 4; jj++) {
        float2 v = unpack2(acc[jj * 4 + kq]);
        vx[jj] = elu1(v.x + bj[jj]);
        vy[jj] = elu1(v.y + bj[jj]);
    }

    if (TO_H3P) {
        *(float4*)(hdst + (2 * kq) * 260 + j0q)     = make_float4(vx[0], vx[1], vx[2], vx[3]);
        *(float4*)(hdst + (2 * kq + 1) * 260 + j0q) = make_float4(vy[0], vy[1], vy[2], vy[3]);
    } else {
        float* wb = hdst + 36 * quadg + 2 * kq;
#pragma unroll
        for (int jj = 0; jj < 4; jj++)
            *(u64*)(wb + 8 * jj) = pack2(vx[jj], vy[jj]);
    }
}

__global__ __launch_bounds__(NTHR, 1)
void ode_main(const float* __restrict__ t, const float* __restrict__ x,
              const float* __restrict__ z, const float* __restrict__ event_t,
              const float* __restrict__ z_jump,
              const float* __restrict__ W1, const float* __restrict__ b1,
              const float* __restrict__ W2, const float* __restrict__ b2,
              const float* __restrict__ W3, const float* __restrict__ b3,
              const float* __restrict__ W4, const float* __restrict__ b4,
              float* __restrict__ out)
{
    extern __shared__ float sm[];
    float* w2c  = sm + OFF_W2;
    float* w3c  = sm + OFF_W3;
    float* strb = sm + OFF_STR;
    float* hA   = sm + OFF_HA;
    float* hB   = sm + OFF_HB;
    float* h3p  = sm + OFF_H3;
    float* w4t  = sm + OFF_W4;
    float* inp  = sm + OFF_INP;
    float* red  = sm + OFF_RED;
    float* zjs  = sm + OFF_ZJ;
    float* evts = sm + OFF_EVT;
    float* b4s  = sm + OFF_B4;
    float* tsh  = sm + OFF_TSH;

    const int tid = threadIdx.x;
    const int b0  = blockIdx.x * 8;
    const unsigned str_u32 = (unsigned)__cvta_generic_to_shared(strb);

    const int lane = tid & 31, warp = tid >> 5;
    const int quadg = warp * 8 + (lane & 7);
    const int j0q   = quadg * 4;
    const int kq    = lane >> 3;
    const int pr  = warp * 16 + (lane & 15);
    const int j0  = pr * 2;
    const int gq  = lane >> 4;
    const int l1w = 16 * pr + ((pr >> 1) * 4);

    for (int idx = tid; idx < ICC * HH; idx += NTHR) { w2c[idx] = W2[idx]; w3c[idx] = W3[idx]; }
    for (int idx = tid; idx < 8 * HH; idx += NTHR) {
        int k = idx >> 8, i = idx & 255;
        w4t[k * 260 + i] = W4[i * 8 + k];
    }
    if (tid < 8) { evts[tid] = event_t[b0 + tid]; b4s[tid] = b4[tid]; }
    if (tid < 64) { int g = tid >> 3, i = tid & 7; zjs[tid] = z_jump[(b0 + g) * 8 + i]; }
    if (tid == 0) { tsh[0] = t[0]; tsh[1] = t[1]; }

    float zreg = 0.f; size_t zbase = 0;
    if (tid >= 64 && tid < 128) {
        int r = tid - 64, g = r >> 3, i = r & 7;
        zbase = (size_t)(b0 + g) * Tt * 8 + i;
    }
    float treg = 0.f;
    if (tid == 192) treg = t[2];

    if (tid < 64) {
        int k = tid & 7, g = tid >> 3;
        float xv = x[(size_t)(b0 + g) * Tt * 8 + k];
        red[k * 8 + g] = xv;
        inp[HROW(k) + g] = xv;
        out[(size_t)(b0 + g) * Tt * 8 + k] = xv;
    } else if (tid < 128) {
        int r = tid - 64, g = r >> 3, zi = r & 7;
        float z0 = z[zbase];
        red[(8 + zi) * 8 + g] = z0;
        zreg = z[zbase + 8];
    }
    __syncthreads();

    if (tid >= 64 && tid < 128) {
        int r = tid - 64, g = r >> 3, zi = r & 7;
        float v = (tsh[0] >= evts[g]) ? zjs[r] : red[(8 + zi) * 8 + g];
        inp[HROW(8 + zi) + g] = v;
    }

    u64 wxz[16];
    u64 cig[4];
    {
        float ca[2][4];
        float cx = b1[j0], cy = b1[j0 + 1];
#pragma unroll
        for (int gp = 0; gp < 4; gp++) { ca[0][gp] = cx; ca[1][gp] = cy; }
#pragma unroll
        for (int i = 0; i < 16; i++) {
            float2 wa = *(const float2*)&W1[i * HH + j0];
            float2 wb = *(const float2*)&W1[(16 + i) * HH + j0];
            float2 wc = *(const float2*)&W1[(32 + i) * HH + j0];
            wxz[i] = pack2(wb.x + wc.x, wb.y + wc.y);
            float dx = wa.x - wb.x, dy = wa.y - wb.y;
#pragma unroll
            for (int gp = 0; gp < 4; gp++) {
                float a = red[i * 8 + gq * 4 + gp];
                ca[0][gp] = fmaf(a, dx, ca[0][gp]);
                ca[1][gp] = fmaf(a, dy, ca[1][gp]);
            }
        }
#pragma unroll
        for (int j = 0; j < 2; j++)
#pragma unroll
            for (int p = 0; p < 2; p++)
                cig[j * 2 + p] = pack2(ca[j][2 * p], ca[j][2 * p + 1]);
    }
    const ulonglong2 b2q = *(const ulonglong2*)&b2[j0q];
    const ulonglong2 b3q = *(const ulonglong2*)&b3[j0q];

    const int c4 = tid >> 6, r4 = tid & 63, k4 = r4 & 7, g4 = r4 >> 3;
    __syncthreads();

    for (int s = 0; s < Tt - 1; s++) {
        const float t0 = tsh[s & 1];
        const float t1 = tsh[(s + 1) & 1];
        const float dt = t1 - t0;

        issue_chunk_w(0, str_u32, W2, W3, warp, lane);
        issue_chunk_w(1, str_u32, W2, W3, warp, lane);
        issue_chunk_w(2, str_u32, W2, W3, warp, lane);

        {
            u64 acc[4] = { cig[0], cig[1], cig[2], cig[3] };
#pragma unroll
            for (int i = 0; i < 16; i++) {
                ulonglong2 hv = *(const ulonglong2*)(inp + HROW(i) + gq * 4);
                float2 wp = unpack2(wxz[i]);
                u64 wd0 = pack2(wp.x, wp.x), wd1 = pack2(wp.y, wp.y);
                acc[0] = ffma2(hv.x, wd0, acc[0]);
                acc[1] = ffma2(hv.y, wd0, acc[1]);
                acc[2] = ffma2(hv.x, wd1, acc[2]);
                acc[3] = ffma2(hv.y, wd1, acc[3]);
            }
#pragma unroll
            for (int j = 0; j < 2; j++) {
                float2 v0 = unpack2(acc[j * 2]);
                float2 v1 = unpack2(acc[j * 2 + 1]);
                *(float4*)(hA + l1w + 8 * j + gq * 4) =
                    make_float4(elu1(v0.x), elu1(v0.y), elu1(v1.x), elu1(v1.y));
            }
        }
        __syncthreads();

        if (tid == 192) {
            if (s + 2 < Tt) tsh[s & 1] = treg;
            if (s + 3 < Tt) treg = t[s + 3];
        }
        float znext = 0.f;
        if (tid >= 64 && tid < 128 && s + 2 < Tt) znext = z[zbase + (size_t)(s + 2) * 8];

        biglayerA<false>(w2c, strb, W2, W3, hA, hB, j0q, kq, quadg, 0, b2q, str_u32, warp, lane);
        __syncthreads();

        biglayerA<true>(w3c, strb, W2, W3, hB, h3p, j0q, kq, quadg, 1, b3q, str_u32, warp, lane);
        __syncthreads();

        {
            float p = 0.f;
            const int base = c4 * 64;
            const float* hp = h3p + g4 * 260 + base;
            const float* wp = w4t + k4 * 260 + base;
#pragma unroll
            for (int it = 0; it < 16; it++) {
                float4 hv = *(const float4*)(hp + it * 4);
                float4 wv = *(const float4*)(wp + it * 4);
                p = fmaf(hv.x, wv.x, p); p = fmaf(hv.y, wv.y, p);
                p = fmaf(hv.z, wv.z, p); p = fmaf(hv.w, wv.w, p);
            }
            red[tid] = p;
        }
        __syncthreads();

        if (tid < 64) {
            int k = tid & 7, g = tid >> 3;
            float o = b4s[k] + red[tid] + red[tid + 64] + red[tid + 128] + red[tid + 192];
            float xn = inp[HROW(k) + g] + dt * o;
            inp[HROW(k) + g] = xn;
            out[(size_t)(b0 + g) * Tt * 8 + (size_t)(s + 1) * 8 + k] = xn;
        } else if (tid < 128) {
            int r = tid - 64, g = r >> 3, zi = r & 7;
            float v = (t1 >= evts[g]) ? zjs[r] : zreg;
            inp[HROW(8 + zi) + g] = v;
            zreg = znext;
        }
        __syncthreads();
    }
}

extern "C" void kernel_launch(void* const* d_in, const int* in_sizes, int n_in,
                              void* d_out, int out_size) {
    const float* t       = (const float*)d_in[0];
    const float* x       = (const float*)d_in[1];
    const float* z       = (const float*)d_in[2];
    const float* event_t = (const float*)d_in[3];
    const float* z_jump  = (const float*)d_in[4];
    const float* W1      = (const float*)d_in[5];
    const float* b1      = (const float*)d_in[6];
    const float* W2      = (const float*)d_in[7];
    const float* b2      = (const float*)d_in[8];
    const float* W3      = (const float*)d_in[9];
    const float* b3      = (const float*)d_in[10];
    const float* W4      = (const float*)d_in[11];
    const float* b4      = (const float*)d_in[12];
    float* out = (float*)d_out;

    cudaFuncSetAttribute(ode_main, cudaFuncAttributeMaxDynamicSharedMemorySize, SM_BYTES);

    ode_main<<<NBLK, NTHR, SM_BYTES>>>(t, x, z, event_t, z_jump,
                                       W1, b1, W2, b2, W3, b3, W4, b4, out);
}

// round 15
// speedup vs baseline: 1.4275x; 1.1237x over previous
#include <cuda_runtime.h>
#include <cstdint>

#define Bt    1024
#define Tt    1000
#define HH    256
#define NBLK  128
#define NTHR  256
#define ICC   88                 // W2/W3 rows cached in SMEM (22 iters of 4)
#define NSTREAM 42               // streamed iters per layer: (256-88)/4
#define NSMAIN  39               // main streamed loop (prefetch dist 3), 13x unroll-3

using u64 = unsigned long long;

__device__ __forceinline__ u64 ffma2(u64 a, u64 b, u64 c) {
    u64 d; asm("fma.rn.f32x2 %0,%1,%2,%3;" : "=l"(d) : "l"(a), "l"(b), "l"(c)); return d;
}
__device__ __forceinline__ u64 addf2(u64 a, u64 b) {
    u64 d; asm("add.rn.f32x2 %0,%1,%2;" : "=l"(d) : "l"(a), "l"(b)); return d;
}
__device__ __forceinline__ u64 pack2(float x, float y) {
    u64 d; asm("mov.b64 %0,{%1,%2};" : "=l"(d) : "f"(x), "f"(y)); return d;
}
__device__ __forceinline__ float2 unpack2(u64 a) {
    float2 f; asm("mov.b64 {%0,%1},%2;" : "=f"(f.x), "=f"(f.y) : "l"(a)); return f;
}
__device__ __forceinline__ float elu1(float v) { return v > 0.f ? v : (__expf(v) - 1.f); }

#define HROW(i) ((i) * 8 + ((i) >> 2) * 4)

#define OFF_W2   0
#define OFF_W3   22528
#define OFF_HA   45056
#define OFF_HB   47360
#define OFF_H3   49664
#define OFF_W4   51744
#define OFF_INP  53824
#define OFF_RED  53968
#define OFF_ZJ   54224
#define OFF_EVT  54288
#define OFF_B4   54296
#define OFF_TSH  54304
#define SM_FLOATS 54306
#define SM_BYTES  (SM_FLOATS * 4)

// w operand from SMEM (cached rows)
__device__ __forceinline__ void accum_iter(const float* __restrict__ w16,
                                           const float* __restrict__ h8,
                                           u64* __restrict__ acc) {
    ulonglong2 w = *(const ulonglong2*)w16;
    float2 wl = unpack2(w.x), wh = unpack2(w.y);
    u64 wd0 = pack2(wl.x, wl.x), wd1 = pack2(wl.y, wl.y);
    u64 wd2 = pack2(wh.x, wh.x), wd3 = pack2(wh.y, wh.y);
    ulonglong2 hlo = *(const ulonglong2*)h8;
    ulonglong2 hhi = *(const ulonglong2*)(h8 + 4);
    acc[0]  = ffma2(hlo.x, wd0, acc[0]);  acc[1]  = ffma2(hlo.y, wd0, acc[1]);
    acc[2]  = ffma2(hhi.x, wd0, acc[2]);  acc[3]  = ffma2(hhi.y, wd0, acc[3]);
    acc[4]  = ffma2(hlo.x, wd1, acc[4]);  acc[5]  = ffma2(hlo.y, wd1, acc[5]);
    acc[6]  = ffma2(hhi.x, wd1, acc[6]);  acc[7]  = ffma2(hhi.y, wd1, acc[7]);
    acc[8]  = ffma2(hlo.x, wd2, acc[8]);  acc[9]  = ffma2(hlo.y, wd2, acc[9]);
    acc[10] = ffma2(hhi.x, wd2, acc[10]); acc[11] = ffma2(hhi.y, wd2, acc[11]);
    acc[12] = ffma2(hlo.x, wd3, acc[12]); acc[13] = ffma2(hlo.y, wd3, acc[13]);
    acc[14] = ffma2(hhi.x, wd3, acc[14]); acc[15] = ffma2(hhi.y, wd3, acc[15]);
}

// w operand in registers (streamed rows via LDG)
__device__ __forceinline__ void accum_rw(float4 wv,
                                         const float* __restrict__ h8,
                                         u64* __restrict__ acc) {
    u64 wd0 = pack2(wv.x, wv.x), wd1 = pack2(wv.y, wv.y);
    u64 wd2 = pack2(wv.z, wv.z), wd3 = pack2(wv.w, wv.w);
    ulonglong2 hlo = *(const ulonglong2*)h8;
    ulonglong2 hhi = *(const ulonglong2*)(h8 + 4);
    acc[0]  = ffma2(hlo.x, wd0, acc[0]);  acc[1]  = ffma2(hlo.y, wd0, acc[1]);
    acc[2]  = ffma2(hhi.x, wd0, acc[2]);  acc[3]  = ffma2(hhi.y, wd0, acc[3]);
    acc[4]  = ffma2(hlo.x, wd1, acc[4]);  acc[5]  = ffma2(hlo.y, wd1, acc[5]);
    acc[6]  = ffma2(hhi.x, wd1, acc[6]);  acc[7]  = ffma2(hhi.y, wd1, acc[7]);
    acc[8]  = ffma2(hlo.x, wd2, acc[8]);  acc[9]  = ffma2(hlo.y, wd2, acc[9]);
    acc[10] = ffma2(hhi.x, wd2, acc[10]); acc[11] = ffma2(hhi.y, wd2, acc[11]);
    acc[12] = ffma2(hlo.x, wd3, acc[12]); acc[13] = ffma2(hlo.y, wd3, acc[13]);
    acc[14] = ffma2(hhi.x, wd3, acc[14]); acc[15] = ffma2(hhi.y, wd3, acc[15]);
}

// full 256->256 layer: cached SMEM rows + L2->register streamed rows
template <bool TO_H3P>
__device__ __forceinline__ void biglayerG(
    const float* __restrict__ wc,      // SMEM cached rows
    const float* __restrict__ Wg,      // global weight matrix
    const float* __restrict__ hsrc, float* __restrict__ hdst,
    int j0q, int kq, int quadg, ulonglong2 bq)
{
    u64 acc[16];
#pragma unroll
    for (int q = 0; q < 16; q++) acc[q] = 0ull;

    const float* wt  = wc + kq * HH + j0q;          // cached lane base
    const float* wgx = Wg + (ICC + kq) * HH + j0q;  // streamed lane base (row ICC+kq)
    const float* ht  = hsrc + kq * 8;               // h lane base

    // prefetch first 3 streamed rows (land during cached loop)
    float4 buf0 = __ldg((const float4*)(wgx + 0 * 4 * HH));
    float4 buf1 = __ldg((const float4*)(wgx + 1 * 4 * HH));
    float4 buf2 = __ldg((const float4*)(wgx + 2 * 4 * HH));

    // cached rows: n = 0..21 (row 4n+kq)
#pragma unroll 4
    for (int n = 0; n < ICC / 4; n++)
        accum_iter(wt + n * 4 * HH, ht + n * 36, acc);

    const float* hts = ht + (ICC / 4) * 36;         // streamed h base

    // streamed main loop: 39 iters, 3-deep register rotation
#pragma unroll 3
    for (int i = 0; i < NSMAIN; i++) {
        float4 wv;
        if (i % 3 == 0)      { wv = buf0; buf0 = __ldg((const float4*)(wgx + (i + 3) * 4 * HH)); }
        else if (i % 3 == 1) { wv = buf1; buf1 = __ldg((const float4*)(wgx + (i + 3) * 4 * HH)); }
        else                 { wv = buf2; buf2 = __ldg((const float4*)(wgx + (i + 3) * 4 * HH)); }
        accum_rw(wv, hts + i * 36, acc);
    }
    // tail: iters 39,40,41 consume remaining buffers
    accum_rw(buf0, hts + 39 * 36, acc);
    accum_rw(buf1, hts + 40 * 36, acc);
    accum_rw(buf2, hts + 41 * 36, acc);

    // K-reduction across kq via shuffles
#pragma unroll
    for (int q = 0; q < 16; q++) {
        acc[q] = addf2(acc[q], __shfl_xor_sync(0xffffffffu, acc[q], 8));
        acc[q] = addf2(acc[q], __shfl_xor_sync(0xffffffffu, acc[q], 16));
    }

    float2 blo = unpack2(bq.x), bhi = unpack2(bq.y);
    const float bj[4] = { blo.x, blo.y, bhi.x, bhi.y };
    float vx[4], vy[4];
#pragma unroll
    for (int jj = 0; jj < 4; jj++) {
        float2 v = unpack2(acc[jj * 4 + kq]);
        vx[jj] = elu1(v.x + bj[jj]);
        vy[jj] = elu1(v.y + bj[jj]);
    }

    if (TO_H3P) {
        *(float4*)(hdst + (2 * kq) * 260 + j0q)     = make_float4(vx[0], vx[1], vx[2], vx[3]);
        *(float4*)(hdst + (2 * kq + 1) * 260 + j0q) = make_float4(vy[0], vy[1], vy[2], vy[3]);
    } else {
        float* wb = hdst + 36 * quadg + 2 * kq;
#pragma unroll
        for (int jj = 0; jj < 4; jj++)
            *(u64*)(wb + 8 * jj) = pack2(vx[jj], vy[jj]);
    }
}

__global__ __launch_bounds__(NTHR, 1)
void ode_main(const float* __restrict__ t, const float* __restrict__ x,
              const float* __restrict__ z, const float* __restrict__ event_t,
              const float* __restrict__ z_jump,
              const float* __restrict__ W1, const float* __restrict__ b1,
              const float* __restrict__ W2, const float* __restrict__ b2,
              const float* __restrict__ W3, const float* __restrict__ b3,
              const float* __restrict__ W4, const float* __restrict__ b4,
              float* __restrict__ out)
{
    extern __shared__ float sm[];
    float* w2c  = sm + OFF_W2;
    float* w3c  = sm + OFF_W3;
    float* hA   = sm + OFF_HA;
    float* hB   = sm + OFF_HB;
    float* h3p  = sm + OFF_H3;
    float* w4t  = sm + OFF_W4;
    float* inp  = sm + OFF_INP;
    float* red  = sm + OFF_RED;
    float* zjs  = sm + OFF_ZJ;
    float* evts = sm + OFF_EVT;
    float* b4s  = sm + OFF_B4;
    float* tsh  = sm + OFF_TSH;

    const int tid = threadIdx.x;
    const int b0  = blockIdx.x * 8;

    const int lane = tid & 31, warp = tid >> 5;
    const int quadg = warp * 8 + (lane & 7);
    const int j0q   = quadg * 4;
    const int kq    = lane >> 3;
    const int pr  = warp * 16 + (lane & 15);
    const int j0  = pr * 2;
    const int gq  = lane >> 4;
    const int l1w = 16 * pr + ((pr >> 1) * 4);

    for (int idx = tid; idx < ICC * HH; idx += NTHR) { w2c[idx] = W2[idx]; w3c[idx] = W3[idx]; }
    for (int idx = tid; idx < 8 * HH; idx += NTHR) {
        int k = idx >> 8, i = idx & 255;
        w4t[k * 260 + i] = W4[i * 8 + k];
    }
    if (tid < 8) { evts[tid] = event_t[b0 + tid]; b4s[tid] = b4[tid]; }
    if (tid < 64) { int g = tid >> 3, i = tid & 7; zjs[tid] = z_jump[(b0 + g) * 8 + i]; }
    if (tid == 0) { tsh[0] = t[0]; tsh[1] = t[1]; }

    float zreg = 0.f; size_t zbase = 0;
    if (tid >= 64 && tid < 128) {
        int r = tid - 64, g = r >> 3, i = r & 7;
        zbase = (size_t)(b0 + g) * Tt * 8 + i;
    }
    float treg = 0.f;
    if (tid == 192) treg = t[2];

    if (tid < 64) {
        int k = tid & 7, g = tid >> 3;
        float xv = x[(size_t)(b0 + g) * Tt * 8 + k];
        red[k * 8 + g] = xv;
        inp[HROW(k) + g] = xv;
        out[(size_t)(b0 + g) * Tt * 8 + k] = xv;
    } else if (tid < 128) {
        int r = tid - 64, g = r >> 3, zi = r & 7;
        float z0 = z[zbase];
        red[(8 + zi) * 8 + g] = z0;
        zreg = z[zbase + 8];
    }
    __syncthreads();

    if (tid >= 64 && tid < 128) {
        int r = tid - 64, g = r >> 3, zi = r & 7;
        float v = (tsh[0] >= evts[g]) ? zjs[r] : red[(8 + zi) * 8 + g];
        inp[HROW(8 + zi) + g] = v;
    }

    u64 wxz[16];
    u64 cig[4];
    {
        float ca[2][4];
        float cx = b1[j0], cy = b1[j0 + 1];
#pragma unroll
        for (int gp = 0; gp < 4; gp++) { ca[0][gp] = cx; ca[1][gp] = cy; }
#pragma unroll
        for (int i = 0; i < 16; i++) {
            float2 wa = *(const float2*)&W1[i * HH + j0];
            float2 wb = *(const float2*)&W1[(16 + i) * HH + j0];
            float2 wc = *(const float2*)&W1[(32 + i) * HH + j0];
            wxz[i] = pack2(wb.x + wc.x, wb.y + wc.y);
            float dx = wa.x - wb.x, dy = wa.y - wb.y;
#pragma unroll
            for (int gp = 0; gp < 4; gp++) {
                float a = red[i * 8 + gq * 4 + gp];
                ca[0][gp] = fmaf(a, dx, ca[0][gp]);
                ca[1][gp] = fmaf(a, dy, ca[1][gp]);
            }
        }
#pragma unroll
        for (int j = 0; j < 2; j++)
#pragma unroll
            for (int p = 0; p < 2; p++)
                cig[j * 2 + p] = pack2(ca[j][2 * p], ca[j][2 * p + 1]);
    }
    const ulonglong2 b2q = *(const ulonglong2*)&b2[j0q];
    const ulonglong2 b3q = *(const ulonglong2*)&b3[j0q];

    const int c4 = tid >> 6, r4 = tid & 63, k4 = r4 & 7, g4 = r4 >> 3;
    __syncthreads();

    for (int s = 0; s < Tt - 1; s++) {
        const float t0 = tsh[s & 1];
        const float t1 = tsh[(s + 1) & 1];
        const float dt = t1 - t0;

        // ---- layer 1 (K=16, folded) ----
        {
            u64 acc[4] = { cig[0], cig[1], cig[2], cig[3] };
#pragma unroll
            for (int i = 0; i < 16; i++) {
                ulonglong2 hv = *(const ulonglong2*)(inp + HROW(i) + gq * 4);
                float2 wp = unpack2(wxz[i]);
                u64 wd0 = pack2(wp.x, wp.x), wd1 = pack2(wp.y, wp.y);
                acc[0] = ffma2(hv.x, wd0, acc[0]);
                acc[1] = ffma2(hv.y, wd0, acc[1]);
                acc[2] = ffma2(hv.x, wd1, acc[2]);
                acc[3] = ffma2(hv.y, wd1, acc[3]);
            }
#pragma unroll
            for (int j = 0; j < 2; j++) {
                float2 v0 = unpack2(acc[j * 2]);
                float2 v1 = unpack2(acc[j * 2 + 1]);
                *(float4*)(hA + l1w + 8 * j + gq * 4) =
                    make_float4(elu1(v0.x), elu1(v0.y), elu1(v1.x), elu1(v1.y));
            }
        }
        __syncthreads();

        if (tid == 192) {
            if (s + 2 < Tt) tsh[s & 1] = treg;
            if (s + 3 < Tt) treg = t[s + 3];
        }
        float znext = 0.f;
        if (tid >= 64 && tid < 128 && s + 2 < Tt) znext = z[zbase + (size_t)(s + 2) * 8];

        // ---- layer 2 ----
        biglayerG<false>(w2c, W2, hA, hB, j0q, kq, quadg, b2q);
        __syncthreads();

        // ---- layer 3 ----
        biglayerG<true>(w3c, W3, hB, h3p, j0q, kq, quadg, b3q);
        __syncthreads();

        // ---- layer 4 partials ----
        {
            float p = 0.f;
            const int base = c4 * 64;
            const float* hp = h3p + g4 * 260 + base;
            const float* wp = w4t + k4 * 260 + base;
#pragma unroll
            for (int it = 0; it < 16; it++) {
                float4 hv = *(const float4*)(hp + it * 4);
                float4 wv = *(const float4*)(wp + it * 4);
                p = fmaf(hv.x, wv.x, p); p = fmaf(hv.y, wv.y, p);
                p = fmaf(hv.z, wv.z, p); p = fmaf(hv.w, wv.w, p);
            }
            red[tid] = p;
        }
        __syncthreads();

        // ---- epilogue ----
        if (tid < 64) {
            int k = tid & 7, g = tid >> 3;
            float o = b4s[k] + red[tid] + red[tid + 64] + red[tid + 128] + red[tid + 192];
            float xn = inp[HROW(k) + g] + dt * o;
            inp[HROW(k) + g] = xn;
            out[(size_t)(b0 + g) * Tt * 8 + (size_t)(s + 1) * 8 + k] = xn;
        } else if (tid < 128) {
            int r = tid - 64, g = r >> 3, zi = r & 7;
            float v = (t1 >= evts[g]) ? zjs[r] : zreg;
            inp[HROW(8 + zi) + g] = v;
            zreg = znext;
        }
        __syncthreads();
    }
}

extern "C" void kernel_launch(void* const* d_in, const int* in_sizes, int n_in,
                              void* d_out, int out_size) {
    const float* t       = (const float*)d_in[0];
    const float* x       = (const float*)d_in[1];
    const float* z       = (const float*)d_in[2];
    const float* event_t = (const float*)d_in[3];
    const float* z_jump  = (const float*)d_in[4];
    const float* W1      = (const float*)d_in[5];
    const float* b1      = (const float*)d_in[6];
    const float* W2      = (const float*)d_in[7];
    const float* b2      = (const float*)d_in[8];
    const float* W3      = (const float*)d_in[9];
    const float* b3      = (const float*)d_in[10];
    const float* W4      = (const float*)d_in[11];
    const float* b4      = (const float*)d_in[12];
    float* out = (float*)d_out;

    cudaFuncSetAttribute(ode_main, cudaFuncAttributeMaxDynamicSharedMemorySize, SM_BYTES);

    ode_main<<<NBLK, NTHR, SM_BYTES>>>(t, x, z, event_t, z_jump,
                                       W1, b1, W2, b2, W3, b3, W4, b4, out);
}

// round 16
// speedup vs baseline: 1.6168x; 1.1326x over previous
#include <cuda_runtime.h>
#include <cstdint>

#define Bt    1024
#define Tt    1000
#define HH    256
#define NBLK  128
#define NTHR  256
#define ICC   88                 // W2/W3 rows cached in SMEM (22 iters of 4)
#define NSTREAM 42               // streamed iters per layer: (256-88)/4
#define PFD   6                  // LDG prefetch depth (rotation)
#define NSMAIN (NSTREAM - PFD)   // 36

using u64 = unsigned long long;

__device__ __forceinline__ u64 ffma2(u64 a, u64 b, u64 c) {
    u64 d; asm("fma.rn.f32x2 %0,%1,%2,%3;" : "=l"(d) : "l"(a), "l"(b), "l"(c)); return d;
}
__device__ __forceinline__ u64 addf2(u64 a, u64 b) {
    u64 d; asm("add.rn.f32x2 %0,%1,%2;" : "=l"(d) : "l"(a), "l"(b)); return d;
}
__device__ __forceinline__ u64 pack2(float x, float y) {
    u64 d; asm("mov.b64 %0,{%1,%2};" : "=l"(d) : "f"(x), "f"(y)); return d;
}
__device__ __forceinline__ float2 unpack2(u64 a) {
    float2 f; asm("mov.b64 {%0,%1},%2;" : "=f"(f.x), "=f"(f.y) : "l"(a)); return f;
}
__device__ __forceinline__ float elu1(float v) { return v > 0.f ? v : (__expf(v) - 1.f); }

#define HROW(i) ((i) * 8 + ((i) >> 2) * 4)

#define OFF_W2   0
#define OFF_W3   22528
#define OFF_HA   45056
#define OFF_HB   47360
#define OFF_H3   49664
#define OFF_W4   51744
#define OFF_INP  53824
#define OFF_RED  53968
#define OFF_ZJ   54224
#define OFF_EVT  54288
#define OFF_B4   54296
#define OFF_TSH  54304
#define SM_FLOATS 54306
#define SM_BYTES  (SM_FLOATS * 4)

// w operand from SMEM (cached rows)
__device__ __forceinline__ void accum_iter(const float* __restrict__ w16,
                                           const float* __restrict__ h8,
                                           u64* __restrict__ acc) {
    ulonglong2 w = *(const ulonglong2*)w16;
    float2 wl = unpack2(w.x), wh = unpack2(w.y);
    u64 wd0 = pack2(wl.x, wl.x), wd1 = pack2(wl.y, wl.y);
    u64 wd2 = pack2(wh.x, wh.x), wd3 = pack2(wh.y, wh.y);
    ulonglong2 hlo = *(const ulonglong2*)h8;
    ulonglong2 hhi = *(const ulonglong2*)(h8 + 4);
    acc[0]  = ffma2(hlo.x, wd0, acc[0]);  acc[1]  = ffma2(hlo.y, wd0, acc[1]);
    acc[2]  = ffma2(hhi.x, wd0, acc[2]);  acc[3]  = ffma2(hhi.y, wd0, acc[3]);
    acc[4]  = ffma2(hlo.x, wd1, acc[4]);  acc[5]  = ffma2(hlo.y, wd1, acc[5]);
    acc[6]  = ffma2(hhi.x, wd1, acc[6]);  acc[7]  = ffma2(hhi.y, wd1, acc[7]);
    acc[8]  = ffma2(hlo.x, wd2, acc[8]);  acc[9]  = ffma2(hlo.y, wd2, acc[9]);
    acc[10] = ffma2(hhi.x, wd2, acc[10]); acc[11] = ffma2(hhi.y, wd2, acc[11]);
    acc[12] = ffma2(hlo.x, wd3, acc[12]); acc[13] = ffma2(hlo.y, wd3, acc[13]);
    acc[14] = ffma2(hhi.x, wd3, acc[14]); acc[15] = ffma2(hhi.y, wd3, acc[15]);
}

// w operand in registers (streamed rows via LDG)
__device__ __forceinline__ void accum_rw(float4 wv,
                                         const float* __restrict__ h8,
                                         u64* __restrict__ acc) {
    u64 wd0 = pack2(wv.x, wv.x), wd1 = pack2(wv.y, wv.y);
    u64 wd2 = pack2(wv.z, wv.z), wd3 = pack2(wv.w, wv.w);
    ulonglong2 hlo = *(const ulonglong2*)h8;
    ulonglong2 hhi = *(const ulonglong2*)(h8 + 4);
    acc[0]  = ffma2(hlo.x, wd0, acc[0]);  acc[1]  = ffma2(hlo.y, wd0, acc[1]);
    acc[2]  = ffma2(hhi.x, wd0, acc[2]);  acc[3]  = ffma2(hhi.y, wd0, acc[3]);
    acc[4]  = ffma2(hlo.x, wd1, acc[4]);  acc[5]  = ffma2(hlo.y, wd1, acc[5]);
    acc[6]  = ffma2(hhi.x, wd1, acc[6]);  acc[7]  = ffma2(hhi.y, wd1, acc[7]);
    acc[8]  = ffma2(hlo.x, wd2, acc[8]);  acc[9]  = ffma2(hlo.y, wd2, acc[9]);
    acc[10] = ffma2(hhi.x, wd2, acc[10]); acc[11] = ffma2(hhi.y, wd2, acc[11]);
    acc[12] = ffma2(hlo.x, wd3, acc[12]); acc[13] = ffma2(hlo.y, wd3, acc[13]);
    acc[14] = ffma2(hhi.x, wd3, acc[14]); acc[15] = ffma2(hhi.y, wd3, acc[15]);
}

// full 256->256 layer: cached SMEM rows + L2->register streamed rows (depth-6 rotation)
template <bool TO_H3P>
__device__ __forceinline__ void biglayerG(
    const float* __restrict__ wc,
    const float* __restrict__ Wg,
    const float* __restrict__ hsrc, float* __restrict__ hdst,
    int j0q, int kq, int quadg, ulonglong2 bq)
{
    u64 acc[16];
#pragma unroll
    for (int q = 0; q < 16; q++) acc[q] = 0ull;

    const float* wt  = wc + kq * HH + j0q;
    const float* wgx = Wg + (ICC + kq) * HH + j0q;
    const float* ht  = hsrc + kq * 8;

    // prefetch first PFD streamed rows (land during cached loop)
    float4 buf[PFD];
#pragma unroll
    for (int p = 0; p < PFD; p++)
        buf[p] = __ldg((const float4*)(wgx + p * 4 * HH));

    // cached rows: n = 0..21 (row 4n+kq)
#pragma unroll 4
    for (int n = 0; n < ICC / 4; n++)
        accum_iter(wt + n * 4 * HH, ht + n * 36, acc);

    const float* hts = ht + (ICC / 4) * 36;

    // streamed main loop: 36 iters, 6-deep register rotation
#pragma unroll 6
    for (int i = 0; i < NSMAIN; i++) {
        float4 wv = buf[i % PFD];
        buf[i % PFD] = __ldg((const float4*)(wgx + (i + PFD) * 4 * HH));
        accum_rw(wv, hts + i * 36, acc);
    }
    // tail: consume remaining PFD buffers
#pragma unroll
    for (int p = 0; p < PFD; p++)
        accum_rw(buf[p], hts + (NSMAIN + p) * 36, acc);

    // K-reduction across kq via shuffles
#pragma unroll
    for (int q = 0; q < 16; q++) {
        acc[q] = addf2(acc[q], __shfl_xor_sync(0xffffffffu, acc[q], 8));
        acc[q] = addf2(acc[q], __shfl_xor_sync(0xffffffffu, acc[q], 16));
    }

    float2 blo = unpack2(bq.x), bhi = unpack2(bq.y);
    const float bj[4] = { blo.x, blo.y, bhi.x, bhi.y };
    float vx[4], vy[4];
#pragma unroll
    for (int jj = 0; jj < 4; jj++) {
        float2 v = unpack2(acc[jj * 4 + kq]);
        vx[jj] = elu1(v.x + bj[jj]);
        vy[jj] = elu1(v.y + bj[jj]);
    }

    if (TO_H3P) {
        *(float4*)(hdst + (2 * kq) * 260 + j0q)     = make_float4(vx[0], vx[1], vx[2], vx[3]);
        *(float4*)(hdst + (2 * kq + 1) * 260 + j0q) = make_float4(vy[0], vy[1], vy[2], vy[3]);
    } else {
        float* wb = hdst + 36 * quadg + 2 * kq;
#pragma unroll
        for (int jj = 0; jj < 4; jj++)
            *(u64*)(wb + 8 * jj) = pack2(vx[jj], vy[jj]);
    }
}

__global__ __launch_bounds__(NTHR, 1)
void ode_main(const float* __restrict__ t, const float* __restrict__ x,
              const float* __restrict__ z, const float* __restrict__ event_t,
              const float* __restrict__ z_jump,
              const float* __restrict__ W1, const float* __restrict__ b1,
              const float* __restrict__ W2, const float* __restrict__ b2,
              const float* __restrict__ W3, const float* __restrict__ b3,
              const float* __restrict__ W4, const float* __restrict__ b4,
              float* __restrict__ out)
{
    extern __shared__ float sm[];
    float* w2c  = sm + OFF_W2;
    float* w3c  = sm + OFF_W3;
    float* hA   = sm + OFF_HA;
    float* hB   = sm + OFF_HB;
    float* h3p  = sm + OFF_H3;
    float* w4t  = sm + OFF_W4;
    float* inp  = sm + OFF_INP;
    float* red  = sm + OFF_RED;
    float* zjs  = sm + OFF_ZJ;
    float* evts = sm + OFF_EVT;
    float* b4s  = sm + OFF_B4;
    float* tsh  = sm + OFF_TSH;

    const int tid = threadIdx.x;
    const int b0  = blockIdx.x * 8;

    const int lane = tid & 31, warp = tid >> 5;
    const int quadg = warp * 8 + (lane & 7);
    const int j0q   = quadg * 4;
    const int kq    = lane >> 3;
    const int pr  = warp * 16 + (lane & 15);
    const int j0  = pr * 2;
    const int gq  = lane >> 4;
    const int l1w = 16 * pr + ((pr >> 1) * 4);

    for (int idx = tid; idx < ICC * HH; idx += NTHR) { w2c[idx] = W2[idx]; w3c[idx] = W3[idx]; }
    for (int idx = tid; idx < 8 * HH; idx += NTHR) {
        int k = idx >> 8, i = idx & 255;
        w4t[k * 260 + i] = W4[i * 8 + k];
    }
    if (tid < 8) { evts[tid] = event_t[b0 + tid]; b4s[tid] = b4[tid]; }
    if (tid < 64) { int g = tid >> 3, i = tid & 7; zjs[tid] = z_jump[(b0 + g) * 8 + i]; }
    if (tid == 0) { tsh[0] = t[0]; tsh[1] = t[1]; }

    float zreg = 0.f; size_t zbase = 0;
    if (tid >= 64 && tid < 128) {
        int r = tid - 64, g = r >> 3, i = r & 7;
        zbase = (size_t)(b0 + g) * Tt * 8 + i;
    }
    float treg = 0.f;
    if (tid == 192) treg = t[2];

    if (tid < 64) {
        int k = tid & 7, g = tid >> 3;
        float xv = x[(size_t)(b0 + g) * Tt * 8 + k];
        red[k * 8 + g] = xv;
        inp[HROW(k) + g] = xv;
        out[(size_t)(b0 + g) * Tt * 8 + k] = xv;
    } else if (tid < 128) {
        int r = tid - 64, g = r >> 3, zi = r & 7;
        float z0 = z[zbase];
        red[(8 + zi) * 8 + g] = z0;
        zreg = z[zbase + 8];
    }
    __syncthreads();

    if (tid >= 64 && tid < 128) {
        int r = tid - 64, g = r >> 3, zi = r & 7;
        float v = (tsh[0] >= evts[g]) ? zjs[r] : red[(8 + zi) * 8 + g];
        inp[HROW(8 + zi) + g] = v;
    }

    u64 wxz[16];
    u64 cig[4];
    {
        float ca[2][4];
        float cx = b1[j0], cy = b1[j0 + 1];
#pragma unroll
        for (int gp = 0; gp < 4; gp++) { ca[0][gp] = cx; ca[1][gp] = cy; }
#pragma unroll
        for (int i = 0; i < 16; i++) {
            float2 wa = *(const float2*)&W1[i * HH + j0];
            float2 wb = *(const float2*)&W1[(16 + i) * HH + j0];
            float2 wc = *(const float2*)&W1[(32 + i) * HH + j0];
            wxz[i] = pack2(wb.x + wc.x, wb.y + wc.y);
            float dx = wa.x - wb.x, dy = wa.y - wb.y;
#pragma unroll
            for (int gp = 0; gp < 4; gp++) {
                float a = red[i * 8 + gq * 4 + gp];
                ca[0][gp] = fmaf(a, dx, ca[0][gp]);
                ca[1][gp] = fmaf(a, dy, ca[1][gp]);
            }
        }
#pragma unroll
        for (int j = 0; j < 2; j++)
#pragma unroll
            for (int p = 0; p < 2; p++)
                cig[j * 2 + p] = pack2(ca[j][2 * p], ca[j][2 * p + 1]);
    }
    const ulonglong2 b2q = *(const ulonglong2*)&b2[j0q];
    const ulonglong2 b3q = *(const ulonglong2*)&b3[j0q];

    const int c4 = tid >> 6, r4 = tid & 63, k4 = r4 & 7, g4 = r4 >> 3;
    __syncthreads();

    for (int s = 0; s < Tt - 1; s++) {
        const float t0 = tsh[s & 1];
        const float t1 = tsh[(s + 1) & 1];
        const float dt = t1 - t0;

        // ---- layer 1 (K=16, folded) ----
        {
            u64 acc[4] = { cig[0], cig[1], cig[2], cig[3] };
#pragma unroll
            for (int i = 0; i < 16; i++) {
                ulonglong2 hv = *(const ulonglong2*)(inp + HROW(i) + gq * 4);
                float2 wp = unpack2(wxz[i]);
                u64 wd0 = pack2(wp.x, wp.x), wd1 = pack2(wp.y, wp.y);
                acc[0] = ffma2(hv.x, wd0, acc[0]);
                acc[1] = ffma2(hv.y, wd0, acc[1]);
                acc[2] = ffma2(hv.x, wd1, acc[2]);
                acc[3] = ffma2(hv.y, wd1, acc[3]);
            }
#pragma unroll
            for (int j = 0; j < 2; j++) {
                float2 v0 = unpack2(acc[j * 2]);
                float2 v1 = unpack2(acc[j * 2 + 1]);
                *(float4*)(hA + l1w + 8 * j + gq * 4) =
                    make_float4(elu1(v0.x), elu1(v0.y), elu1(v1.x), elu1(v1.y));
            }
        }
        __syncthreads();

        if (tid == 192) {
            if (s + 2 < Tt) tsh[s & 1] = treg;
            if (s + 3 < Tt) treg = t[s + 3];
        }
        float znext = 0.f;
        if (tid >= 64 && tid < 128 && s + 2 < Tt) znext = z[zbase + (size_t)(s + 2) * 8];

        // ---- layer 2 ----
        biglayerG<false>(w2c, W2, hA, hB, j0q, kq, quadg, b2q);
        __syncthreads();

        // ---- layer 3 ----
        biglayerG<true>(w3c, W3, hB, h3p, j0q, kq, quadg, b3q);
        __syncthreads();

        // ---- layer 4 partials ----
        {
            float p = 0.f;
            const int base = c4 * 64;
            const float* hp = h3p + g4 * 260 + base;
            const float* wp = w4t + k4 * 260 + base;
#pragma unroll
            for (int it = 0; it < 16; it++) {
                float4 hv = *(const float4*)(hp + it * 4);
                float4 wv = *(const float4*)(wp + it * 4);
                p = fmaf(hv.x, wv.x, p); p = fmaf(hv.y, wv.y, p);
                p = fmaf(hv.z, wv.z, p); p = fmaf(hv.w, wv.w, p);
            }
            red[tid] = p;
        }
        __syncthreads();

        // ---- epilogue ----
        if (tid < 64) {
            int k = tid & 7, g = tid >> 3;
            float o = b4s[k] + red[tid] + red[tid + 64] + red[tid + 128] + red[tid + 192];
            float xn = inp[HROW(k) + g] + dt * o;
            inp[HROW(k) + g] = xn;
            out[(size_t)(b0 + g) * Tt * 8 + (size_t)(s + 1) * 8 + k] = xn;
        } else if (tid < 128) {
            int r = tid - 64, g = r >> 3, zi = r & 7;
            float v = (t1 >= evts[g]) ? zjs[r] : zreg;
            inp[HROW(8 + zi) + g] = v;
            zreg = znext;
        }
        __syncthreads();
    }
}

extern "C" void kernel_launch(void* const* d_in, const int* in_sizes, int n_in,
                              void* d_out, int out_size) {
    const float* t       = (const float*)d_in[0];
    const float* x       = (const float*)d_in[1];
    const float* z       = (const float*)d_in[2];
    const float* event_t = (const float*)d_in[3];
    const float* z_jump  = (const float*)d_in[4];
    const float* W1      = (const float*)d_in[5];
    const float* b1      = (const float*)d_in[6];
    const float* W2      = (const float*)d_in[7];
    const float* b2      = (const float*)d_in[8];
    const float* W3      = (const float*)d_in[9];
    const float* b3      = (const float*)d_in[10];
    const float* W4      = (const float*)d_in[11];
    const float* b4      = (const float*)d_in[12];
    float* out = (float*)d_out;

    cudaFuncSetAttribute(ode_main, cudaFuncAttributeMaxDynamicSharedMemorySize, SM_BYTES);

    ode_main<<<NBLK, NTHR, SM_BYTES>>>(t, x, z, event_t, z_jump,
                                       W1, b1, W2, b2, W3, b3, W4, b4, out);
}